// round 4
// baseline (speedup 1.0000x reference)
#include <cuda_runtime.h>
#include <cuda_bf16.h>

// WaveletLinear: y[b,o] = sum_i w[o,i] * (1 - s^2) * exp(-0.5 s^2),
//   s = (x[b,i] - t[o,i]) / (A_MIN + softplus(scale_raw[o,i]) + EPS)
// B=512, O=1024, I=512.
//
// Math:  c^2 = 1/(2 ln2),  u = (c*s)^2  (>=0)
//   exp(-0.5 s^2) = 2^(-u)   computed via PACKED half2 MUFU (ex2.approx.f16x2)
//   w*(1 - s^2)   = fma(w2n, u, w),  w2n = -2ln2*w,  w = w2n * (-1/(2ln2))
// MUFU work halved vs f32 ex2: 2 exps per MUFU slot. fma stays packed f32x2.

#define I_DIM 512
#define RB 8   // batch rows per warp

typedef unsigned long long u64;

__device__ float g_ivc[1024 * 512];
__device__ float g_tin[1024 * 512];
__device__ float g_w2n[1024 * 512];

__device__ __forceinline__ u64 fma2(u64 a, u64 b, u64 c) {
    u64 d; asm("fma.rn.f32x2 %0, %1, %2, %3;" : "=l"(d) : "l"(a), "l"(b), "l"(c)); return d;
}
__device__ __forceinline__ u64 mul2(u64 a, u64 b) {
    u64 d; asm("mul.rn.f32x2 %0, %1, %2;" : "=l"(d) : "l"(a), "l"(b)); return d;
}
__device__ __forceinline__ u64 pack2(float lo, float hi) {
    u64 d; asm("mov.b64 %0, {%1, %2};" : "=l"(d) : "f"(lo), "f"(hi)); return d;
}
__device__ __forceinline__ float lo32(u64 v) { return __uint_as_float((unsigned)v); }
__device__ __forceinline__ float hi32(u64 v) { return __uint_as_float((unsigned)(v >> 32)); }

// packed f32x2 -> 2^(-u) for both lanes, via f16x2 MUFU, back to packed f32x2
__device__ __forceinline__ u64 exp2n_h2(u64 u) {
    u64 r;
    asm("{\n\t"
        ".reg .b32 lo, hi, h;\n\t"
        ".reg .b16 e0, e1;\n\t"
        ".reg .f32 f0, f1;\n\t"
        "mov.b64 {lo, hi}, %1;\n\t"
        "cvt.rn.f16x2.f32 h, hi, lo;\n\t"   // upper=hi, lower=lo
        "neg.f16x2 h, h;\n\t"
        "ex2.approx.f16x2 h, h;\n\t"        // 2 exps, 1 MUFU slot
        "mov.b32 {e0, e1}, h;\n\t"          // e0=lower(lo), e1=upper(hi)
        "cvt.f32.f16 f0, e0;\n\t"
        "cvt.f32.f16 f1, e1;\n\t"
        "mov.b64 %0, {f0, f1};\n\t"
        "}" : "=l"(r) : "l"(u));
    return r;
}

#define C_FOLD   0.84932180028801905f    // sqrt(1/(2 ln2))
#define TWO_LN2  1.38629436111989062f    // 2 ln2
#define NINV2LN2 (-0.72134752044448170f) // -1/(2 ln2)

__global__ void prep_kernel(const float* __restrict__ t,
                            const float* __restrict__ sraw,
                            const float* __restrict__ w,
                            int n)
{
    int idx = blockIdx.x * blockDim.x + threadIdx.x;
    if (idx < n) {
        float z  = sraw[idx];
        float sp = log1pf(__expf(z));
        float sc = 0.001f + sp + 1e-8f;
        float iv = 1.0f / sc;
        g_ivc[idx] = C_FOLD * iv;
        g_tin[idx] = -C_FOLD * t[idx] * iv;
        g_w2n[idx] = -TWO_LN2 * w[idx];
    }
}

__global__ __launch_bounds__(256, 3)
void wavelet_kernel(const float* __restrict__ x,
                    float* __restrict__ out,
                    int O)
{
    const int warp = (blockIdx.x * 256 + threadIdx.x) >> 5;
    const int lane = threadIdx.x & 31;
    const int o  = warp >> 6;       // 8 warps (one block) share o
    const int bt = warp & 63;
    const int b0 = bt * RB;

    const ulonglong2* __restrict__ ivp = (const ulonglong2*)(g_ivc + (size_t)o * I_DIM);
    const ulonglong2* __restrict__ tnp = (const ulonglong2*)(g_tin + (size_t)o * I_DIM);
    const ulonglong2* __restrict__ w2p = (const ulonglong2*)(g_w2n + (size_t)o * I_DIM);
    const ulonglong2* __restrict__ xp  = (const ulonglong2*)(x     + (size_t)b0 * I_DIM);

    const u64 KINV = pack2(NINV2LN2, NINV2LN2);

    u64 acc[RB];
#pragma unroll
    for (int b = 0; b < RB; b++) acc[b] = 0ull;

#pragma unroll
    for (int step = 0; step < I_DIM / 128; step++) {
        const int i4 = step * 32 + lane;   // 128-bit index: 128 i per step
        const ulonglong2 iv = ivp[i4];
        const ulonglong2 tn = tnp[i4];
        const ulonglong2 w2 = w2p[i4];
        // reconstruct w from w2n once per step (shared by all RB rows)
        const u64 wvx = mul2(w2.x, KINV);
        const u64 wvy = mul2(w2.y, KINV);

#pragma unroll
        for (int b = 0; b < RB; b++) {
            const ulonglong2 xv = xp[i4 + b * (I_DIM / 4)];

            // pair 0
            {
                u64 s  = fma2(xv.x, iv.x, tn.x);
                u64 u  = mul2(s, s);
                u64 ep = exp2n_h2(u);
                u64 pp = fma2(w2.x, u, wvx);
                acc[b] = fma2(pp, ep, acc[b]);
            }
            // pair 1
            {
                u64 s  = fma2(xv.y, iv.y, tn.y);
                u64 u  = mul2(s, s);
                u64 ep = exp2n_h2(u);
                u64 pp = fma2(w2.y, u, wvy);
                acc[b] = fma2(pp, ep, acc[b]);
            }
        }
    }

    // fold packed halves, then warp reduction over i-lanes
#pragma unroll
    for (int b = 0; b < RB; b++) {
        float a = lo32(acc[b]) + hi32(acc[b]);
#pragma unroll
        for (int off = 16; off > 0; off >>= 1)
            a += __shfl_xor_sync(0xFFFFFFFFu, a, off);
        if (lane == 0)
            out[(size_t)(b0 + b) * O + o] = a;
    }
}

extern "C" void kernel_launch(void* const* d_in, const int* in_sizes, int n_in,
                              void* d_out, int out_size)
{
    const float* x    = (const float*)d_in[0];  // (B, I)
    const float* t    = (const float*)d_in[1];  // (O, I)
    const float* sraw = (const float*)d_in[2];  // (O, I)
    const float* w    = (const float*)d_in[3];  // (O, I)
    float* out = (float*)d_out;                 // (B, O)

    const int OI = in_sizes[1];          // O * I
    const int BI = in_sizes[0];          // B * I
    const int O  = OI / I_DIM;           // 1024
    const int B  = BI / I_DIM;           // 512
    const int nbt = B / RB;              // 64

    prep_kernel<<<(OI + 255) / 256, 256>>>(t, sraw, w, OI);

    const int total_warps = O * nbt;
    wavelet_kernel<<<total_warps / 8, 256>>>(x, out, O);
}

// round 5
// speedup vs baseline: 1.0501x; 1.0501x over previous
#include <cuda_runtime.h>
#include <cuda_bf16.h>

// WaveletLinear: y[b,o] = sum_i w[o,i] * (1 - s^2) * exp(-0.5 s^2),
//   s = (x[b,i] - t[o,i]) / (A_MIN + softplus(scale_raw[o,i]) + EPS)
// B=512, O=1024, I=512.
//
// Math:  c^2 = 1/(2 ln2),  u = (c*s)^2  (>=0)
//   exp(-0.5 s^2) = 2^(-u)
//   w*(1 - s^2)   = fma(w2n, u, w),  w2n = -2ln2*w,  w = w2n * (-1/(2ln2))
//
// Hybrid exp: alternate pairs between f32 MUFU (2 EX2 slots, no overhead)
// and f16x2 MUFU (1 slot, +cvt overhead) to balance MUFU vs issue/ALU.

#define I_DIM 512
#define RB 8   // batch rows per warp

typedef unsigned long long u64;

__device__ float g_ivc[1024 * 512];
__device__ float g_tin[1024 * 512];
__device__ float g_w2n[1024 * 512];

__device__ __forceinline__ u64 fma2(u64 a, u64 b, u64 c) {
    u64 d; asm("fma.rn.f32x2 %0, %1, %2, %3;" : "=l"(d) : "l"(a), "l"(b), "l"(c)); return d;
}
__device__ __forceinline__ u64 mul2(u64 a, u64 b) {
    u64 d; asm("mul.rn.f32x2 %0, %1, %2;" : "=l"(d) : "l"(a), "l"(b)); return d;
}
__device__ __forceinline__ float ex2neg(float a) {
    float r;
    asm("{ .reg .f32 t; neg.f32 t, %1; ex2.approx.ftz.f32 %0, t; }" : "=f"(r) : "f"(a));
    return r;
}
__device__ __forceinline__ u64 pack2(float lo, float hi) {
    u64 d; asm("mov.b64 %0, {%1, %2};" : "=l"(d) : "f"(lo), "f"(hi)); return d;
}
__device__ __forceinline__ float lo32(u64 v) { return __uint_as_float((unsigned)v); }
__device__ __forceinline__ float hi32(u64 v) { return __uint_as_float((unsigned)(v >> 32)); }

// packed f32x2 u -> 2^(-u) in packed f32x2, via one f16x2 MUFU slot
__device__ __forceinline__ u64 exp2n_h2(u64 u) {
    u64 r;
    asm("{\n\t"
        ".reg .b32 lo, hi, h;\n\t"
        ".reg .b16 e0, e1;\n\t"
        ".reg .f32 f0, f1;\n\t"
        "mov.b64 {lo, hi}, %1;\n\t"
        "cvt.rn.f16x2.f32 h, hi, lo;\n\t"
        "neg.f16x2 h, h;\n\t"
        "ex2.approx.f16x2 h, h;\n\t"
        "mov.b32 {e0, e1}, h;\n\t"
        "cvt.f32.f16 f0, e0;\n\t"
        "cvt.f32.f16 f1, e1;\n\t"
        "mov.b64 %0, {f0, f1};\n\t"
        "}" : "=l"(r) : "l"(u));
    return r;
}

#define C_FOLD   0.84932180028801905f    // sqrt(1/(2 ln2))
#define TWO_LN2  1.38629436111989062f    // 2 ln2
#define NINV2LN2 (-0.72134752044448170f) // -1/(2 ln2)

__global__ void prep_kernel(const float* __restrict__ t,
                            const float* __restrict__ sraw,
                            const float* __restrict__ w,
                            int n)
{
    int idx = blockIdx.x * blockDim.x + threadIdx.x;
    if (idx < n) {
        float z  = sraw[idx];
        float sp = log1pf(__expf(z));
        float sc = 0.001f + sp + 1e-8f;
        float iv = 1.0f / sc;
        g_ivc[idx] = C_FOLD * iv;
        g_tin[idx] = -C_FOLD * t[idx] * iv;
        g_w2n[idx] = -TWO_LN2 * w[idx];
    }
}

__global__ __launch_bounds__(256, 3)
void wavelet_kernel(const float* __restrict__ x,
                    float* __restrict__ out,
                    int O)
{
    const int warp = (blockIdx.x * 256 + threadIdx.x) >> 5;
    const int lane = threadIdx.x & 31;
    const int o  = warp >> 6;       // 8 warps (one block) share o
    const int bt = warp & 63;
    const int b0 = bt * RB;

    const ulonglong2* __restrict__ ivp = (const ulonglong2*)(g_ivc + (size_t)o * I_DIM);
    const ulonglong2* __restrict__ tnp = (const ulonglong2*)(g_tin + (size_t)o * I_DIM);
    const ulonglong2* __restrict__ w2p = (const ulonglong2*)(g_w2n + (size_t)o * I_DIM);
    const ulonglong2* __restrict__ xp  = (const ulonglong2*)(x     + (size_t)b0 * I_DIM);

    const u64 KINV = pack2(NINV2LN2, NINV2LN2);

    u64 acc[RB];
#pragma unroll
    for (int b = 0; b < RB; b++) acc[b] = 0ull;

#pragma unroll
    for (int step = 0; step < I_DIM / 128; step++) {
        const int i4 = step * 32 + lane;   // 128-bit index: 128 i per step
        const ulonglong2 iv = ivp[i4];
        const ulonglong2 tn = tnp[i4];
        const ulonglong2 w2 = w2p[i4];
        // reconstruct w from w2n once per step (shared by all RB rows)
        const u64 wvx = mul2(w2.x, KINV);
        const u64 wvy = mul2(w2.y, KINV);

#pragma unroll
        for (int b = 0; b < RB; b++) {
            const ulonglong2 xv = xp[i4 + b * (I_DIM / 4)];

            // pair 0: f32 MUFU path (2 EX2 slots, no conversion overhead)
            {
                u64 s  = fma2(xv.x, iv.x, tn.x);
                u64 u  = mul2(s, s);
                float e0 = ex2neg(lo32(u));
                float e1 = ex2neg(hi32(u));
                u64 ep = pack2(e0, e1);
                u64 pp = fma2(w2.x, u, wvx);
                acc[b] = fma2(pp, ep, acc[b]);
            }
            // pair 1: f16x2 MUFU path (1 slot + cvts)
            {
                u64 s  = fma2(xv.y, iv.y, tn.y);
                u64 u  = mul2(s, s);
                u64 ep = exp2n_h2(u);
                u64 pp = fma2(w2.y, u, wvy);
                acc[b] = fma2(pp, ep, acc[b]);
            }
        }
    }

    // fold packed halves, then warp reduction over i-lanes
#pragma unroll
    for (int b = 0; b < RB; b++) {
        float a = lo32(acc[b]) + hi32(acc[b]);
#pragma unroll
        for (int off = 16; off > 0; off >>= 1)
            a += __shfl_xor_sync(0xFFFFFFFFu, a, off);
        if (lane == 0)
            out[(size_t)(b0 + b) * O + o] = a;
    }
}

extern "C" void kernel_launch(void* const* d_in, const int* in_sizes, int n_in,
                              void* d_out, int out_size)
{
    const float* x    = (const float*)d_in[0];  // (B, I)
    const float* t    = (const float*)d_in[1];  // (O, I)
    const float* sraw = (const float*)d_in[2];  // (O, I)
    const float* w    = (const float*)d_in[3];  // (O, I)
    float* out = (float*)d_out;                 // (B, O)

    const int OI = in_sizes[1];          // O * I
    const int BI = in_sizes[0];          // B * I
    const int O  = OI / I_DIM;           // 1024
    const int B  = BI / I_DIM;           // 512
    const int nbt = B / RB;              // 64

    prep_kernel<<<(OI + 255) / 256, 256>>>(t, sraw, w, OI);

    const int total_warps = O * nbt;
    wavelet_kernel<<<total_warps / 8, 256>>>(x, out, O);
}

// round 6
// speedup vs baseline: 1.0644x; 1.0136x over previous
#include <cuda_runtime.h>
#include <cuda_bf16.h>

// WaveletLinear: y[b,o] = sum_i w[o,i] * (1 - s^2) * exp(-0.5 s^2),
//   s = (x[b,i] - t[o,i]) / (A_MIN + softplus(scale_raw[o,i]) + EPS)
// B=512, O=1024, I=512.
//
// Math:  u = (c*s)^2, c^2 = 1/(2 ln2):
//   exp(-0.5 s^2) = 2^(-u);  w*(1-s^2) = fma(w2n, u, w), w2n = -2ln2*w
// Hybrid exp: half the pairs via f32 MUFU, half via packed f16x2 MUFU.
//
// Layout: block = 8 warps sharing one batch tile (8 x rows, L1-hit across
// warps), each warp owns a distinct o. Params interleaved per (o,step):
// [iv x128][tn x128][w2 x128] -> one base reg + immediates.

#define I_DIM 512
#define RB 8   // batch rows per warp

typedef unsigned long long u64;

// 6 MB: [o][step][plane][lane4]  (1536 floats per o)
__device__ float g_prm[1024 * 1536];

__device__ __forceinline__ u64 fma2(u64 a, u64 b, u64 c) {
    u64 d; asm("fma.rn.f32x2 %0, %1, %2, %3;" : "=l"(d) : "l"(a), "l"(b), "l"(c)); return d;
}
__device__ __forceinline__ u64 mul2(u64 a, u64 b) {
    u64 d; asm("mul.rn.f32x2 %0, %1, %2;" : "=l"(d) : "l"(a), "l"(b)); return d;
}
__device__ __forceinline__ float ex2neg(float a) {
    float r;
    asm("{ .reg .f32 t; neg.f32 t, %1; ex2.approx.ftz.f32 %0, t; }" : "=f"(r) : "f"(a));
    return r;
}
__device__ __forceinline__ u64 pack2(float lo, float hi) {
    u64 d; asm("mov.b64 %0, {%1, %2};" : "=l"(d) : "f"(lo), "f"(hi)); return d;
}
__device__ __forceinline__ float lo32(u64 v) { return __uint_as_float((unsigned)v); }
__device__ __forceinline__ float hi32(u64 v) { return __uint_as_float((unsigned)(v >> 32)); }

// packed f32x2 u -> 2^(-u) packed f32x2, one f16x2 MUFU slot
__device__ __forceinline__ u64 exp2n_h2(u64 u) {
    u64 r;
    asm("{\n\t"
        ".reg .b32 lo, hi, h;\n\t"
        ".reg .b16 e0, e1;\n\t"
        ".reg .f32 f0, f1;\n\t"
        "mov.b64 {lo, hi}, %1;\n\t"
        "cvt.rn.f16x2.f32 h, hi, lo;\n\t"
        "neg.f16x2 h, h;\n\t"
        "ex2.approx.f16x2 h, h;\n\t"
        "mov.b32 {e0, e1}, h;\n\t"
        "cvt.f32.f16 f0, e0;\n\t"
        "cvt.f32.f16 f1, e1;\n\t"
        "mov.b64 %0, {f0, f1};\n\t"
        "}" : "=l"(r) : "l"(u));
    return r;
}

#define C_FOLD   0.84932180028801905f    // sqrt(1/(2 ln2))
#define TWO_LN2  1.38629436111989062f    // 2 ln2
#define NINV2LN2 (-0.72134752044448170f) // -1/(2 ln2)

__global__ void prep_kernel(const float* __restrict__ t,
                            const float* __restrict__ sraw,
                            const float* __restrict__ w,
                            int n)
{
    int idx = blockIdx.x * blockDim.x + threadIdx.x;
    if (idx < n) {
        int o = idx >> 9;          // / 512
        int i = idx & 511;
        int step = i >> 7;
        int l    = i & 127;
        int base = o * 1536 + step * 384 + l;

        float z  = sraw[idx];
        float sp = log1pf(__expf(z));
        float sc = 0.001f + sp + 1e-8f;
        float iv = 1.0f / sc;
        g_prm[base      ] = C_FOLD * iv;             // iv plane
        g_prm[base + 128] = -C_FOLD * t[idx] * iv;   // tn plane
        g_prm[base + 256] = -TWO_LN2 * w[idx];       // w2n plane
    }
}

__global__ __launch_bounds__(256, 4)
void wavelet_kernel(const float* __restrict__ x,
                    float* __restrict__ out,
                    int O)
{
    const int wid  = threadIdx.x >> 5;
    const int lane = threadIdx.x & 31;
    const int og = blockIdx.x & 127;   // o-group varies fastest -> co-resident
    const int bt = blockIdx.x >> 7;    // blocks share the same x tile
    const int o  = og * 8 + wid;
    const int b0 = bt * RB;

    const float* pb = g_prm + (size_t)o * 1536 + lane * 4;
    const float* xb = x + (size_t)b0 * I_DIM + lane * 4;

    const u64 KINV = pack2(NINV2LN2, NINV2LN2);

    u64 acc[RB];
#pragma unroll
    for (int b = 0; b < RB; b++) acc[b] = 0ull;

#pragma unroll
    for (int step = 0; step < 4; step++) {
        const ulonglong2 iv = *(const ulonglong2*)(pb + step * 384);
        const ulonglong2 tn = *(const ulonglong2*)(pb + step * 384 + 128);
        const ulonglong2 w2 = *(const ulonglong2*)(pb + step * 384 + 256);
        const u64 wvx = mul2(w2.x, KINV);   // reconstruct w once per step
        const u64 wvy = mul2(w2.y, KINV);

#pragma unroll
        for (int b = 0; b < RB; b++) {
            const ulonglong2 xv = *(const ulonglong2*)(xb + step * 128 + b * I_DIM);

            // pair 0: f32 MUFU (2 EX2 slots, no conversion overhead)
            {
                u64 s  = fma2(xv.x, iv.x, tn.x);
                u64 u  = mul2(s, s);
                float e0 = ex2neg(lo32(u));
                float e1 = ex2neg(hi32(u));
                u64 ep = pack2(e0, e1);
                u64 pp = fma2(w2.x, u, wvx);
                acc[b] = fma2(pp, ep, acc[b]);
            }
            // pair 1: f16x2 MUFU (1 slot + cvts)
            {
                u64 s  = fma2(xv.y, iv.y, tn.y);
                u64 u  = mul2(s, s);
                u64 ep = exp2n_h2(u);
                u64 pp = fma2(w2.y, u, wvy);
                acc[b] = fma2(pp, ep, acc[b]);
            }
        }
    }

    // fold packed halves, then warp reduction over i-lanes
#pragma unroll
    for (int b = 0; b < RB; b++) {
        float a = lo32(acc[b]) + hi32(acc[b]);
#pragma unroll
        for (int off = 16; off > 0; off >>= 1)
            a += __shfl_xor_sync(0xFFFFFFFFu, a, off);
        if (lane == 0)
            out[(size_t)(b0 + b) * O + o] = a;
    }
}

extern "C" void kernel_launch(void* const* d_in, const int* in_sizes, int n_in,
                              void* d_out, int out_size)
{
    const float* x    = (const float*)d_in[0];  // (B, I)
    const float* t    = (const float*)d_in[1];  // (O, I)
    const float* sraw = (const float*)d_in[2];  // (O, I)
    const float* w    = (const float*)d_in[3];  // (O, I)
    float* out = (float*)d_out;                 // (B, O)

    const int OI = in_sizes[1];          // O * I = 524288
    const int BI = in_sizes[0];          // B * I
    const int O  = OI / I_DIM;           // 1024
    const int B  = BI / I_DIM;           // 512
    const int nbt = B / RB;              // 64

    prep_kernel<<<(OI + 255) / 256, 256>>>(t, sraw, w, OI);

    // blocks = o_groups(128) * bt(64) = 8192
    wavelet_kernel<<<(O / 8) * nbt, 256>>>(x, out, O);
}

// round 7
// speedup vs baseline: 1.0768x; 1.0116x over previous
#include <cuda_runtime.h>
#include <cuda_bf16.h>

// WaveletLinear: y[b,o] = sum_i w[o,i] * (1 - s^2) * exp(-0.5 s^2),
//   s = (x[b,i] - t[o,i]) / (A_MIN + softplus(scale_raw[o,i]) + EPS)
// B=512, O=1024, I=512.
//
// Math:  c^2 = 1/(2 ln2),  u = (c*s)^2  (>=0)
//   exp(-0.5 s^2) = ex2(-u)          (pure f32 MUFU; neg folds into operand)
//   w*(1 - s^2)   = fma(w2n, u, w),  w2n = -2ln2*w,  w = w2n * (-1/(2ln2))
// Round-3 structure (proven fastest: MUFU-bound at 88% efficiency) with
// __launch_bounds__(256,4) to lift occupancy 35% -> ~47%.

#define I_DIM 512
#define RB 8   // batch rows per warp

typedef unsigned long long u64;

__device__ float g_ivc[1024 * 512];
__device__ float g_tin[1024 * 512];
__device__ float g_w2n[1024 * 512];

__device__ __forceinline__ u64 fma2(u64 a, u64 b, u64 c) {
    u64 d; asm("fma.rn.f32x2 %0, %1, %2, %3;" : "=l"(d) : "l"(a), "l"(b), "l"(c)); return d;
}
__device__ __forceinline__ u64 mul2(u64 a, u64 b) {
    u64 d; asm("mul.rn.f32x2 %0, %1, %2;" : "=l"(d) : "l"(a), "l"(b)); return d;
}
__device__ __forceinline__ float ex2neg(float a) {
    float r;
    asm("{ .reg .f32 t; neg.f32 t, %1; ex2.approx.ftz.f32 %0, t; }" : "=f"(r) : "f"(a));
    return r;
}
__device__ __forceinline__ u64 pack2(float lo, float hi) {
    u64 d; asm("mov.b64 %0, {%1, %2};" : "=l"(d) : "f"(lo), "f"(hi)); return d;
}
__device__ __forceinline__ float lo32(u64 v) { return __uint_as_float((unsigned)v); }
__device__ __forceinline__ float hi32(u64 v) { return __uint_as_float((unsigned)(v >> 32)); }

#define C_FOLD   0.84932180028801905f    // sqrt(1/(2 ln2))
#define TWO_LN2  1.38629436111989062f    // 2 ln2
#define NINV2LN2 (-0.72134752044448170f) // -1/(2 ln2)

__global__ void prep_kernel(const float* __restrict__ t,
                            const float* __restrict__ sraw,
                            const float* __restrict__ w,
                            int n)
{
    int idx = blockIdx.x * blockDim.x + threadIdx.x;
    if (idx < n) {
        float z  = sraw[idx];
        float sp = log1pf(__expf(z));
        float sc = 0.001f + sp + 1e-8f;
        float iv = 1.0f / sc;
        g_ivc[idx] = C_FOLD * iv;
        g_tin[idx] = -C_FOLD * t[idx] * iv;
        g_w2n[idx] = -TWO_LN2 * w[idx];
    }
}

__global__ __launch_bounds__(256, 4)
void wavelet_kernel(const float* __restrict__ x,
                    float* __restrict__ out,
                    int O)
{
    const int warp = (blockIdx.x * 256 + threadIdx.x) >> 5;
    const int lane = threadIdx.x & 31;
    const int o  = warp >> 6;       // 8 warps (one block) share o
    const int bt = warp & 63;
    const int b0 = bt * RB;

    const ulonglong2* __restrict__ ivp = (const ulonglong2*)(g_ivc + (size_t)o * I_DIM);
    const ulonglong2* __restrict__ tnp = (const ulonglong2*)(g_tin + (size_t)o * I_DIM);
    const ulonglong2* __restrict__ w2p = (const ulonglong2*)(g_w2n + (size_t)o * I_DIM);
    const ulonglong2* __restrict__ xp  = (const ulonglong2*)(x     + (size_t)b0 * I_DIM);

    const u64 KINV = pack2(NINV2LN2, NINV2LN2);

    u64 acc[RB];
#pragma unroll
    for (int b = 0; b < RB; b++) acc[b] = 0ull;

#pragma unroll
    for (int step = 0; step < I_DIM / 128; step++) {
        const int i4 = step * 32 + lane;   // 128-bit index: 128 i per step
        const ulonglong2 iv = ivp[i4];
        const ulonglong2 tn = tnp[i4];
        const ulonglong2 w2 = w2p[i4];
        // reconstruct w from w2n once per step (shared by all RB rows)
        const u64 wvx = mul2(w2.x, KINV);
        const u64 wvy = mul2(w2.y, KINV);

#pragma unroll
        for (int b = 0; b < RB; b++) {
            const ulonglong2 xv = xp[i4 + b * (I_DIM / 4)];

            // pair 0
            {
                u64 s  = fma2(xv.x, iv.x, tn.x);
                u64 u  = mul2(s, s);
                float e0 = ex2neg(lo32(u));
                float e1 = ex2neg(hi32(u));
                u64 ep = pack2(e0, e1);
                u64 pp = fma2(w2.x, u, wvx);
                acc[b] = fma2(pp, ep, acc[b]);
            }
            // pair 1
            {
                u64 s  = fma2(xv.y, iv.y, tn.y);
                u64 u  = mul2(s, s);
                float e0 = ex2neg(lo32(u));
                float e1 = ex2neg(hi32(u));
                u64 ep = pack2(e0, e1);
                u64 pp = fma2(w2.y, u, wvy);
                acc[b] = fma2(pp, ep, acc[b]);
            }
        }
    }

    // fold packed halves, then warp reduction over i-lanes
#pragma unroll
    for (int b = 0; b < RB; b++) {
        float a = lo32(acc[b]) + hi32(acc[b]);
#pragma unroll
        for (int off = 16; off > 0; off >>= 1)
            a += __shfl_xor_sync(0xFFFFFFFFu, a, off);
        if (lane == 0)
            out[(size_t)(b0 + b) * O + o] = a;
    }
}

extern "C" void kernel_launch(void* const* d_in, const int* in_sizes, int n_in,
                              void* d_out, int out_size)
{
    const float* x    = (const float*)d_in[0];  // (B, I)
    const float* t    = (const float*)d_in[1];  // (O, I)
    const float* sraw = (const float*)d_in[2];  // (O, I)
    const float* w    = (const float*)d_in[3];  // (O, I)
    float* out = (float*)d_out;                 // (B, O)

    const int OI = in_sizes[1];          // O * I
    const int BI = in_sizes[0];          // B * I
    const int O  = OI / I_DIM;           // 1024
    const int B  = BI / I_DIM;           // 512
    const int nbt = B / RB;              // 64

    prep_kernel<<<(OI + 255) / 256, 256>>>(t, sraw, w, OI);

    const int total_warps = O * nbt;
    wavelet_kernel<<<total_warps / 8, 256>>>(x, out, O);
}